// round 11
// baseline (speedup 1.0000x reference)
#include <cuda_runtime.h>
#include <cuda_bf16.h>
#include <math.h>
#include <stdint.h>

#define B_BATCH 64
#define N_SEQ   512
#define D_MOD   512
#define H_HEADS 8
#define DK_HEAD 64
#define BN_TOT  32768
#define SLOT    16777216u

// fp32 arena: ff2 only
__device__ float g_arena[SLOT];
__device__ float g_psum[256 * 512];
__device__ float g_psq[256 * 512];
__device__ float g_gamma[512],  g_beta[512];    // BN2
__device__ float g_gamma1[512], g_beta1[512];   // BN1 saved
__device__ float g_b1eff[512];

#define WOFF_QKV 0u
#define WOFF_WO  786432u
#define WOFF_FF1 1048576u
#define WOFF_FF2 1310720u
__device__ __align__(128) __nv_bfloat16 g_wbf_hi[1572864];
__device__ __align__(128) __nv_bfloat16 g_wbf_lo[1572864];

// bf16 hi/lo activation streams [m][512] (Vt: [h][b][dv][512])
__device__ __align__(128) __nv_bfloat16 g_xh[16777216],  g_xl[16777216];
__device__ __align__(128) __nv_bfloat16 g_qh[16777216],  g_ql[16777216];
__device__ __align__(128) __nv_bfloat16 g_kh[16777216],  g_kl[16777216];
__device__ __align__(128) __nv_bfloat16 g_vth[16777216], g_vtl[16777216];
__device__ __align__(128) __nv_bfloat16 g_hdh[16777216], g_hdl[16777216];  // heads
__device__ __align__(128) __nv_bfloat16 g_ph[16777216],  g_pl[16777216];   // proj
__device__ __align__(128) __nv_bfloat16 g_f1h[16777216], g_f1l[16777216];  // ff1

// ===========================================================================
// Helpers
// ===========================================================================
__device__ __forceinline__ uint32_t smem_u32(const void* p) {
    uint32_t a;
    asm("{ .reg .u64 t; cvta.to.shared.u64 t, %1; cvt.u32.u64 %0, t; }" : "=r"(a) : "l"(p));
    return a;
}
__device__ __forceinline__ void ldsm_x4(uint32_t* r, uint32_t addr) {
    asm volatile("ldmatrix.sync.aligned.m8n8.x4.shared.b16 {%0,%1,%2,%3}, [%4];"
        : "=r"(r[0]), "=r"(r[1]), "=r"(r[2]), "=r"(r[3]) : "r"(addr));
}
__device__ __forceinline__ void mma16816(float* c, const uint32_t* a, const uint32_t* b) {
    asm volatile("mma.sync.aligned.m16n8k16.row.col.f32.bf16.bf16.f32 "
        "{%0,%1,%2,%3}, {%4,%5,%6,%7}, {%8,%9}, {%0,%1,%2,%3};"
        : "+f"(c[0]), "+f"(c[1]), "+f"(c[2]), "+f"(c[3])
        : "r"(a[0]), "r"(a[1]), "r"(a[2]), "r"(a[3]), "r"(b[0]), "r"(b[1]));
}
__device__ __forceinline__ uint32_t pack2(__nv_bfloat16 a, __nv_bfloat16 b) {
    return (uint32_t)__bfloat16_as_ushort(a) | ((uint32_t)__bfloat16_as_ushort(b) << 16);
}
__device__ __forceinline__ __nv_bfloat16 bhi(float v) { return __float2bfloat16_rn(v); }
__device__ __forceinline__ __nv_bfloat16 blo(float v, __nv_bfloat16 h) {
    return __float2bfloat16_rn(v - __bfloat162float(h));
}
__device__ __forceinline__ uint32_t sw128b(uint32_t row, uint32_t cb) {
    return row * 128 + (cb ^ ((row & 7u) << 4));
}
__device__ __forceinline__ uint32_t sw32b(uint32_t row, uint32_t cb) {
    return (row >> 1) * 128 + ((((row & 1u) << 6) | cb) ^ (((row >> 1) & 7u) << 4));
}
#define CP16(dst, src) \
    asm volatile("cp.async.cg.shared.global [%0], [%1], 16;" :: "r"(dst), "l"(src) : "memory")
#define CP_COMMIT() asm volatile("cp.async.commit_group;" ::: "memory")
#define CP_WAIT0()  asm volatile("cp.async.wait_group 0;" ::: "memory")
#define CP_WAIT1()  asm volatile("cp.async.wait_group 1;" ::: "memory")

extern __shared__ char dynsm[];

// ===========================================================================
// Fused QKV (cp.async double-buffered). Block = (m-tile 128, head h).
// ===========================================================================
#define QKV_SMEM 81920
__global__ __launch_bounds__(256) void k_mm_qkv3()
{
    const uint32_t sb = smem_u32(dynsm);
    const int h = blockIdx.y;
    const int m0 = blockIdx.x * 128;
    const int tid = threadIdx.x, lane = tid & 31, wid = tid >> 5;
    const int wm = wid >> 1, wn = wid & 1;
    const int t8 = lane >> 3, lr = lane & 7;

    auto stage = [&](int c, uint32_t bufb) {
#pragma unroll
        for (int it = 0; it < 4; it++) {
            int idx = it * 256 + tid;
            int arr = idx >> 9, rem = idx & 511;
            int row = rem >> 2, f8 = rem & 3;
            const __nv_bfloat16* src = (arr ? g_xl : g_xh)
                + (size_t)(m0 + row) * 512 + c * 32 + f8 * 8;
            CP16(bufb + arr * 8192 + sw32b(row, f8 * 16), src);
        }
#pragma unroll
        for (int it = 0; it < 6; it++) {
            int idx = it * 256 + tid;
            int which = idx >> 9, rem = idx & 511;
            int hl = rem >> 8, r2 = rem & 255;
            int row = r2 >> 2, f8 = r2 & 3;
            const __nv_bfloat16* src = (hl ? g_wbf_lo : g_wbf_hi)
                + (size_t)(which * 8 + h) * 32768 + (size_t)row * 512 + c * 32 + f8 * 8;
            CP16(bufb + 16384 + which * 8192 + hl * 4096 + sw32b(row, f8 * 16), src);
        }
        CP_COMMIT();
    };

    float acc[3][2][4][4];
#pragma unroll
    for (int q = 0; q < 3; q++)
#pragma unroll
        for (int i = 0; i < 2; i++)
#pragma unroll
            for (int j = 0; j < 4; j++)
#pragma unroll
                for (int k = 0; k < 4; k++) acc[q][i][j][k] = 0.f;

    stage(0, sb);
    stage(1, sb + 40960);

    for (int c = 0; c < 16; c++) {
        if (c == 15) CP_WAIT0(); else CP_WAIT1();
        __syncthreads();
        const uint32_t bufb = sb + (uint32_t)(c & 1) * 40960;
#pragma unroll
        for (int s = 0; s < 2; s++) {
            uint32_t ah[2][4], al[2][4];
#pragma unroll
            for (int msub = 0; msub < 2; msub++) {
                uint32_t row = (uint32_t)(wm * 32 + msub * 16 + ((t8 & 1) << 3) + lr);
                uint32_t cb  = ((uint32_t)s << 5) + (((uint32_t)t8 >> 1) << 4);
                uint32_t off = sw32b(row, cb);
                ldsm_x4(ah[msub], bufb + off);
                ldsm_x4(al[msub], bufb + 8192 + off);
            }
#pragma unroll
            for (int q = 0; q < 3; q++) {
                uint32_t bh[2][4], bl[2][4];
#pragma unroll
                for (int nsub = 0; nsub < 2; nsub++) {
                    uint32_t row = (uint32_t)(wn * 32 + nsub * 16 + ((t8 >> 1) << 3) + lr);
                    uint32_t cb  = ((uint32_t)s << 5) + (((uint32_t)t8 & 1u) << 4);
                    uint32_t off = sw32b(row, cb);
                    ldsm_x4(bh[nsub], bufb + 16384 + q * 8192 + off);
                    ldsm_x4(bl[nsub], bufb + 16384 + q * 8192 + 4096 + off);
                }
#pragma unroll
                for (int msub = 0; msub < 2; msub++)
#pragma unroll
                    for (int n8 = 0; n8 < 4; n8++) {
                        const uint32_t* bhp = &bh[n8 >> 1][(n8 & 1) * 2];
                        const uint32_t* blp = &bl[n8 >> 1][(n8 & 1) * 2];
                        mma16816(acc[q][msub][n8], ah[msub], bhp);
                        mma16816(acc[q][msub][n8], ah[msub], blp);
                        mma16816(acc[q][msub][n8], al[msub], bhp);
                    }
            }
        }
        __syncthreads();
        if (c + 2 < 16) stage(c + 2, sb + (uint32_t)(c & 1) * 40960);
    }

    float* ep = (float*)dynsm;                  // 128 x 65 fp32
    const int g = lane >> 2, tq = lane & 3;
    const int b = m0 >> 9, n0 = m0 & 511;
    const size_t vtoff = (size_t)(h * 64 + b) * 32768;

#pragma unroll
    for (int q = 0; q < 3; q++) {
        __syncthreads();
#pragma unroll
        for (int msub = 0; msub < 2; msub++)
#pragma unroll
            for (int n8 = 0; n8 < 4; n8++)
#pragma unroll
                for (int i = 0; i < 4; i++) {
                    int row = wm * 32 + msub * 16 + ((i >> 1) << 3) + g;
                    int col = wn * 32 + n8 * 8 + tq * 2 + (i & 1);
                    ep[row * 65 + col] = acc[q][msub][n8][i];
                }
        __syncthreads();
        if (q < 2) {
            __nv_bfloat16* Dh = q ? g_kh : g_qh;
            __nv_bfloat16* Dl = q ? g_kl : g_ql;
            int mr = tid >> 4, kq = tid & 15;
#pragma unroll
            for (int it = 0; it < 8; it++) {
                int m = it * 16 + mr;
                float fx = ep[m * 65 + kq * 4 + 0];
                float fy = ep[m * 65 + kq * 4 + 1];
                float fz = ep[m * 65 + kq * 4 + 2];
                float fw = ep[m * 65 + kq * 4 + 3];
                __nv_bfloat16 h0 = bhi(fx), h1 = bhi(fy), h2 = bhi(fz), h3 = bhi(fw);
                size_t o = ((size_t)h * BN_TOT + (size_t)(m0 + m)) * 64 + kq * 4;
                *(uint2*)(Dh + o) = make_uint2(pack2(h0, h1), pack2(h2, h3));
                *(uint2*)(Dl + o) = make_uint2(pack2(blo(fx, h0), blo(fy, h1)),
                                               pack2(blo(fz, h2), blo(fw, h3)));
            }
        } else {
            int nn = (tid & 15) * 8;
#pragma unroll
            for (int p = 0; p < 4; p++) {
                int dv = p * 16 + (tid >> 4);
                __nv_bfloat16 hs[8], ls[8];
#pragma unroll
                for (int j = 0; j < 8; j++) {
                    float v = ep[(nn + j) * 65 + dv];
                    hs[j] = bhi(v);
                    ls[j] = blo(v, hs[j]);
                }
                size_t o = vtoff + (size_t)dv * 512 + n0 + nn;
                *(uint4*)(g_vth + o) = make_uint4(pack2(hs[0], hs[1]), pack2(hs[2], hs[3]),
                                                  pack2(hs[4], hs[5]), pack2(hs[6], hs[7]));
                *(uint4*)(g_vtl + o) = make_uint4(pack2(ls[0], ls[1]), pack2(ls[2], ls[3]),
                                                  pack2(ls[4], ls[5]), pack2(ls[6], ls[7]));
            }
        }
    }
}

// ===========================================================================
// HMMA flash attention, cp.async double-buffered K/V.
// ===========================================================================
#define ATTN_SMEM 98304
__global__ __launch_bounds__(256) void k_attn_mma()
{
    const uint32_t sb = smem_u32(dynsm);
    const int h = blockIdx.z, b = blockIdx.y, q0 = blockIdx.x * 128;
    const int tid = threadIdx.x, lane = tid & 31, w = tid >> 5;
    const int t8 = lane >> 3, lr = lane & 7;

    const size_t qbase = ((size_t)h * BN_TOT + (size_t)b * 512 + q0) * 64;
    const size_t kbase = ((size_t)h * BN_TOT + (size_t)b * 512) * 64;
    const size_t vtoff = (size_t)(h * 64 + b) * 32768;

    auto stage_kv = [&](int kt, uint32_t bufb) {
#pragma unroll
        for (int it = 0; it < 8; it++) {
            int idx = it * 256 + tid;
            int arr = idx >> 9, rem = idx & 511;
            int row = rem >> 3, f8 = rem & 7;
            const __nv_bfloat16* src;
            if (arr == 0)      src = g_kh  + kbase + (size_t)(kt * 64 + row) * 64 + f8 * 8;
            else if (arr == 1) src = g_kl  + kbase + (size_t)(kt * 64 + row) * 64 + f8 * 8;
            else if (arr == 2) src = g_vth + vtoff + (size_t)row * 512 + kt * 64 + f8 * 8;
            else               src = g_vtl + vtoff + (size_t)row * 512 + kt * 64 + f8 * 8;
            CP16(bufb + arr * 8192 + sw128b(row, f8 * 16), src);
        }
        CP_COMMIT();
    };

#pragma unroll
    for (int it = 0; it < 8; it++) {
        int idx = it * 256 + tid;
        int arr = idx >> 10, rem = idx & 1023;
        int row = rem >> 3, f8 = rem & 7;
        const __nv_bfloat16* src = (arr ? g_ql : g_qh) + qbase + (size_t)row * 64 + f8 * 8;
        *(uint4*)(dynsm + arr * 16384 + sw128b(row, f8 * 16)) = *(const uint4*)src;
    }
    stage_kv(0, sb + 32768);
    stage_kv(1, sb + 65536);
    __syncthreads();

    uint32_t qh[4][4], ql[4][4];
#pragma unroll
    for (int s = 0; s < 4; s++) {
        uint32_t row = (uint32_t)(w * 16 + ((t8 & 1) << 3) + lr);
        uint32_t cb  = ((uint32_t)s << 5) + (((uint32_t)t8 >> 1) << 4);
        uint32_t off = sw128b(row, cb);
        ldsm_x4(qh[s], sb + off);
        ldsm_x4(ql[s], sb + 16384 + off);
    }

    float o[8][4];
#pragma unroll
    for (int n8 = 0; n8 < 8; n8++)
#pragma unroll
        for (int i = 0; i < 4; i++) o[n8][i] = 0.f;
    float m0_ = -1e30f, m1_ = -1e30f, l0 = 0.f, l1 = 0.f;

    for (int kt = 0; kt < 8; kt++) {
        if (kt == 7) CP_WAIT0(); else CP_WAIT1();
        __syncthreads();
        const uint32_t kvb = sb + 32768 + (uint32_t)(kt & 1) * 32768;

        float s[8][4];
#pragma unroll
        for (int n8 = 0; n8 < 8; n8++)
#pragma unroll
            for (int i = 0; i < 4; i++) s[n8][i] = 0.f;
#pragma unroll
        for (int ks = 0; ks < 4; ks++) {
            uint32_t bh[4][4], bl[4][4];
#pragma unroll
            for (int nsub = 0; nsub < 4; nsub++) {
                uint32_t row = (uint32_t)(nsub * 16 + ((t8 >> 1) << 3) + lr);
                uint32_t cb  = ((uint32_t)ks << 5) + (((uint32_t)t8 & 1u) << 4);
                uint32_t off = sw128b(row, cb);
                ldsm_x4(bh[nsub], kvb + off);
                ldsm_x4(bl[nsub], kvb + 8192 + off);
            }
#pragma unroll
            for (int n8 = 0; n8 < 8; n8++) {
                const uint32_t* bhp = &bh[n8 >> 1][(n8 & 1) * 2];
                const uint32_t* blp = &bl[n8 >> 1][(n8 & 1) * 2];
                mma16816(s[n8], qh[ks], bhp);
                mma16816(s[n8], qh[ks], blp);
                mma16816(s[n8], ql[ks], bhp);
            }
        }

        float mx0 = -1e30f, mx1 = -1e30f;
#pragma unroll
        for (int n8 = 0; n8 < 8; n8++) {
            s[n8][0] *= 0.125f; s[n8][1] *= 0.125f; s[n8][2] *= 0.125f; s[n8][3] *= 0.125f;
            mx0 = fmaxf(mx0, fmaxf(s[n8][0], s[n8][1]));
            mx1 = fmaxf(mx1, fmaxf(s[n8][2], s[n8][3]));
        }
        mx0 = fmaxf(mx0, __shfl_xor_sync(0xffffffffu, mx0, 1));
        mx0 = fmaxf(mx0, __shfl_xor_sync(0xffffffffu, mx0, 2));
        mx1 = fmaxf(mx1, __shfl_xor_sync(0xffffffffu, mx1, 1));
        mx1 = fmaxf(mx1, __shfl_xor_sync(0xffffffffu, mx1, 2));
        float mn0 = fmaxf(m0_, mx0), mn1 = fmaxf(m1_, mx1);
        float a0 = __expf(m0_ - mn0), a1 = __expf(m1_ - mn1);
        m0_ = mn0; m1_ = mn1;
        float rs0 = 0.f, rs1 = 0.f;
#pragma unroll
        for (int n8 = 0; n8 < 8; n8++) {
            s[n8][0] = __expf(s[n8][0] - mn0); s[n8][1] = __expf(s[n8][1] - mn0);
            s[n8][2] = __expf(s[n8][2] - mn1); s[n8][3] = __expf(s[n8][3] - mn1);
            rs0 += s[n8][0] + s[n8][1];
            rs1 += s[n8][2] + s[n8][3];
        }
        rs0 += __shfl_xor_sync(0xffffffffu, rs0, 1);
        rs0 += __shfl_xor_sync(0xffffffffu, rs0, 2);
        rs1 += __shfl_xor_sync(0xffffffffu, rs1, 1);
        rs1 += __shfl_xor_sync(0xffffffffu, rs1, 2);
        l0 = l0 * a0 + rs0;
        l1 = l1 * a1 + rs1;
#pragma unroll
        for (int n8 = 0; n8 < 8; n8++) {
            o[n8][0] *= a0; o[n8][1] *= a0; o[n8][2] *= a1; o[n8][3] *= a1;
        }

        uint32_t ph[4][4], pl[4][4];
#pragma unroll
        for (int ks = 0; ks < 4; ks++) {
            int na = 2 * ks, nb = 2 * ks + 1;
            __nv_bfloat16 h0 = bhi(s[na][0]), h1 = bhi(s[na][1]),
                          h2 = bhi(s[na][2]), h3 = bhi(s[na][3]);
            __nv_bfloat16 h4 = bhi(s[nb][0]), h5 = bhi(s[nb][1]),
                          h6 = bhi(s[nb][2]), h7 = bhi(s[nb][3]);
            ph[ks][0] = pack2(h0, h1); ph[ks][1] = pack2(h2, h3);
            ph[ks][2] = pack2(h4, h5); ph[ks][3] = pack2(h6, h7);
            pl[ks][0] = pack2(blo(s[na][0], h0), blo(s[na][1], h1));
            pl[ks][1] = pack2(blo(s[na][2], h2), blo(s[na][3], h3));
            pl[ks][2] = pack2(blo(s[nb][0], h4), blo(s[nb][1], h5));
            pl[ks][3] = pack2(blo(s[nb][2], h6), blo(s[nb][3], h7));
        }

#pragma unroll
        for (int ks = 0; ks < 4; ks++) {
            uint32_t vh[4][4], vl[4][4];
#pragma unroll
            for (int nsub = 0; nsub < 4; nsub++) {
                uint32_t row = (uint32_t)(nsub * 16 + ((t8 >> 1) << 3) + lr);
                uint32_t cb  = ((uint32_t)ks << 5) + (((uint32_t)t8 & 1u) << 4);
                uint32_t off = sw128b(row, cb);
                ldsm_x4(vh[nsub], kvb + 16384 + off);
                ldsm_x4(vl[nsub], kvb + 24576 + off);
            }
#pragma unroll
            for (int n8 = 0; n8 < 8; n8++) {
                const uint32_t* vhp = &vh[n8 >> 1][(n8 & 1) * 2];
                const uint32_t* vlp = &vl[n8 >> 1][(n8 & 1) * 2];
                mma16816(o[n8], ph[ks], vhp);
                mma16816(o[n8], ph[ks], vlp);
                mma16816(o[n8], pl[ks], vhp);
            }
        }
        __syncthreads();
        if (kt + 2 < 8) stage_kv(kt + 2, sb + 32768 + (uint32_t)(kt & 1) * 32768);
    }

    float inv0 = 1.f / l0, inv1 = 1.f / l1;
    float* ep = (float*)dynsm;
    int r0 = lane >> 2, c2 = (lane & 3) * 2;
#pragma unroll
    for (int n8 = 0; n8 < 8; n8++) {
        ep[(w * 16 + r0) * 65 + n8 * 8 + c2]     = o[n8][0] * inv0;
        ep[(w * 16 + r0) * 65 + n8 * 8 + c2 + 1] = o[n8][1] * inv0;
        ep[(w * 16 + r0 + 8) * 65 + n8 * 8 + c2]     = o[n8][2] * inv1;
        ep[(w * 16 + r0 + 8) * 65 + n8 * 8 + c2 + 1] = o[n8][3] * inv1;
    }
    __syncthreads();
    int mr = tid >> 4, kq = tid & 15;
#pragma unroll
    for (int it = 0; it < 8; it++) {
        int m = it * 16 + mr;
        float fx = ep[m * 65 + kq * 4 + 0];
        float fy = ep[m * 65 + kq * 4 + 1];
        float fz = ep[m * 65 + kq * 4 + 2];
        float fw = ep[m * 65 + kq * 4 + 3];
        __nv_bfloat16 h0 = bhi(fx), h1 = bhi(fy), h2 = bhi(fz), h3 = bhi(fw);
        size_t row = (size_t)b * 512 + q0 + m;
        size_t oo = row * 512 + h * 64 + kq * 4;
        *(uint2*)(g_hdh + oo) = make_uint2(pack2(h0, h1), pack2(h2, h3));
        *(uint2*)(g_hdl + oo) = make_uint2(pack2(blo(fx, h0), blo(fy, h1)),
                                           pack2(blo(fz, h2), blo(fw, h3)));
    }
}

// ===========================================================================
// Unified bf16-in GEMM. which: 0=proj(+BN1 stats, hi/lo out)
//                              1=ff1(folded W, b1eff bias, relu, hi/lo out)
//                              2=ff2(fp32 out, bias)
// ===========================================================================
__global__ __launch_bounds__(256) void k_mm_bf(int which, const float* __restrict__ bias)
{
    __shared__ __align__(1024) char sm[49152];
    const uint32_t sb = smem_u32(sm);
    const int tid = threadIdx.x, lane = tid & 31, wid = tid >> 5;
    const int wm = wid >> 1, wn = wid & 1;
    const int t8 = lane >> 3, lr = lane & 7;
    const int m0 = blockIdx.x * 128, n0 = blockIdx.y * 64;

    const __nv_bfloat16 *Ah, *Al;
    unsigned boff;
    if (which == 0)      { Ah = g_hdh; Al = g_hdl; boff = WOFF_WO;  }
    else if (which == 1) { Ah = g_ph;  Al = g_pl;  boff = WOFF_FF1; }
    else                 { Ah = g_f1h; Al = g_f1l; boff = WOFF_FF2; }

    auto stage = [&](int c, uint32_t bufb) {
#pragma unroll
        for (int it = 0; it < 4; it++) {
            int idx = it * 256 + tid;
            int arr = idx >> 9, rem = idx & 511;
            int row = rem >> 2, f8 = rem & 3;
            const __nv_bfloat16* src = (arr ? Al : Ah)
                + (size_t)(m0 + row) * 512 + c * 32 + f8 * 8;
            CP16(bufb + arr * 8192 + sw32b(row, f8 * 16), src);
        }
#pragma unroll
        for (int it = 0; it < 2; it++) {
            int idx = it * 256 + tid;
            int hl = idx >> 8, rem = idx & 255;
            int row = rem >> 2, f8 = rem & 3;
            const __nv_bfloat16* src = (hl ? g_wbf_lo : g_wbf_hi)
                + boff + (size_t)(n0 + row) * 512 + c * 32 + f8 * 8;
            CP16(bufb + 16384 + hl * 4096 + sw32b(row, f8 * 16), src);
        }
        CP_COMMIT();
    };

    float acc[2][4][4];
#pragma unroll
    for (int i = 0; i < 2; i++)
#pragma unroll
        for (int j = 0; j < 4; j++)
#pragma unroll
            for (int k = 0; k < 4; k++) acc[i][j][k] = 0.f;

    stage(0, sb);
    stage(1, sb + 24576);

    for (int c = 0; c < 16; c++) {
        if (c == 15) CP_WAIT0(); else CP_WAIT1();
        __syncthreads();
        const uint32_t bufb = sb + (uint32_t)(c & 1) * 24576;
#pragma unroll
        for (int s = 0; s < 2; s++) {
            uint32_t ah[2][4], al[2][4], bh[2][4], bl[2][4];
#pragma unroll
            for (int msub = 0; msub < 2; msub++) {
                uint32_t row = (uint32_t)(wm * 32 + msub * 16 + ((t8 & 1) << 3) + lr);
                uint32_t cb  = ((uint32_t)s << 5) + (((uint32_t)t8 >> 1) << 4);
                uint32_t off = sw32b(row, cb);
                ldsm_x4(ah[msub], bufb + off);
                ldsm_x4(al[msub], bufb + 8192 + off);
            }
#pragma unroll
            for (int nsub = 0; nsub < 2; nsub++) {
                uint32_t row = (uint32_t)(wn * 32 + nsub * 16 + ((t8 >> 1) << 3) + lr);
                uint32_t cb  = ((uint32_t)s << 5) + (((uint32_t)t8 & 1u) << 4);
                uint32_t off = sw32b(row, cb);
                ldsm_x4(bh[nsub], bufb + 16384 + off);
                ldsm_x4(bl[nsub], bufb + 20480 + off);
            }
#pragma unroll
            for (int msub = 0; msub < 2; msub++)
#pragma unroll
                for (int n8 = 0; n8 < 4; n8++) {
                    const uint32_t* bhp = &bh[n8 >> 1][(n8 & 1) * 2];
                    const uint32_t* blp = &bl[n8 >> 1][(n8 & 1) * 2];
                    mma16816(acc[msub][n8], ah[msub], bhp);
                    mma16816(acc[msub][n8], ah[msub], blp);
                    mma16816(acc[msub][n8], al[msub], bhp);
                }
        }
        __syncthreads();
        if (c + 2 < 16) stage(c + 2, sb + (uint32_t)(c & 1) * 24576);
    }

    float* ep = (float*)sm;                     // 128 x 65; scratch after
    int g = lane >> 2, tq = lane & 3;
#pragma unroll
    for (int msub = 0; msub < 2; msub++)
#pragma unroll
        for (int n8 = 0; n8 < 4; n8++)
#pragma unroll
            for (int i = 0; i < 4; i++) {
                int row = wm * 32 + msub * 16 + ((i >> 1) << 3) + g;
                int col = wn * 32 + n8 * 8 + tq * 2 + (i & 1);
                ep[row * 65 + col] = acc[msub][n8][i];
            }
    __syncthreads();

    // fused BN1 partial stats for proj (unique (m-chunk, col) per block)
    if (which == 0) {
        int c = tid & 63, qrt = tid >> 6;
        float s1 = 0.f, s2 = 0.f;
#pragma unroll 8
        for (int r = qrt * 32; r < qrt * 32 + 32; r++) {
            float v = ep[r * 65 + c];
            s1 += v; s2 += v * v;
        }
        float* scr = ep + 128 * 65;
        scr[qrt * 64 + c] = s1;
        scr[256 + qrt * 64 + c] = s2;
    }

    int mr = tid >> 4, kq = tid & 15;
    float4 bb = make_float4(0.f, 0.f, 0.f, 0.f);
    if (which == 1)      bb = *(const float4*)&g_b1eff[n0 + kq * 4];
    else if (which == 2) bb = *(const float4*)&bias[n0 + kq * 4];
#pragma unroll
    for (int it = 0; it < 8; it++) {
        int m = it * 16 + mr;
        float fx = ep[m * 65 + kq * 4 + 0] + bb.x;
        float fy = ep[m * 65 + kq * 4 + 1] + bb.y;
        float fz = ep[m * 65 + kq * 4 + 2] + bb.z;
        float fw = ep[m * 65 + kq * 4 + 3] + bb.w;
        if (which == 1) {
            fx = fmaxf(fx, 0.f); fy = fmaxf(fy, 0.f);
            fz = fmaxf(fz, 0.f); fw = fmaxf(fw, 0.f);
        }
        size_t oo = (size_t)(m0 + m) * 512 + n0 + kq * 4;
        if (which == 2) {
            *(float4*)(g_arena + oo) = make_float4(fx, fy, fz, fw);
        } else {
            __nv_bfloat16* Ch = which ? g_f1h : g_ph;
            __nv_bfloat16* Cl = which ? g_f1l : g_pl;
            __nv_bfloat16 h0 = bhi(fx), h1 = bhi(fy), h2 = bhi(fz), h3 = bhi(fw);
            *(uint2*)(Ch + oo) = make_uint2(pack2(h0, h1), pack2(h2, h3));
            *(uint2*)(Cl + oo) = make_uint2(pack2(blo(fx, h0), blo(fy, h1)),
                                            pack2(blo(fz, h2), blo(fw, h3)));
        }
    }

    if (which == 0) {
        __syncthreads();
        if (tid < 64) {
            float* scr = ep + 128 * 65;
            float a = scr[tid] + scr[64 + tid] + scr[128 + tid] + scr[192 + tid];
            float b2 = scr[256 + tid] + scr[320 + tid] + scr[384 + tid] + scr[448 + tid];
            // stats on t = 2*proj
            g_psum[blockIdx.x * 512 + n0 + tid] = 2.f * a;
            g_psq[blockIdx.x * 512 + n0 + tid]  = 4.f * b2;
        }
    }
}

// ===========================================================================
// Prep kernels
// ===========================================================================
__device__ __forceinline__ void wsplit(size_t o, float v) {
    __nv_bfloat16 h = __float2bfloat16_rn(v);
    g_wbf_hi[o] = h;
    g_wbf_lo[o] = __float2bfloat16_rn(v - __bfloat162float(h));
}
__global__ __launch_bounds__(256) void k_prep_qkv(const float* __restrict__ Wq,
    const float* __restrict__ Wk, const float* __restrict__ Wv)
{
    int z = blockIdx.y, which = z >> 3, h = z & 7;
    const float* W = (which == 0 ? Wq : (which == 1 ? Wk : Wv)) + (size_t)h * 32768;
    int i = blockIdx.x * 256 + threadIdx.x;
    int dk = i >> 9, dd = i & 511;
    wsplit((size_t)WOFF_QKV + (size_t)z * 32768 + i, W[dd * 64 + dk]);
}
__global__ __launch_bounds__(256) void k_prep_wo(const float* __restrict__ Wo)
{
    int i = blockIdx.x * 256 + threadIdx.x;
    int dd = i >> 9, hdk = i & 511;
    wsplit((size_t)WOFF_WO + i, Wo[hdk * 512 + dd]);
}
__global__ __launch_bounds__(256) void k_prep_ff2(const float* __restrict__ w2)
{
    int i = blockIdx.x * 256 + threadIdx.x;    // 262144
    wsplit((size_t)WOFF_FF2 + i, w2[i]);
}
__global__ __launch_bounds__(256) void k_prep_x(const float* __restrict__ x)
{
    size_t i = ((size_t)blockIdx.x * 256 + threadIdx.x) * 4;   // 16777216 total
    float4 v = *(const float4*)(x + i);
    __nv_bfloat16 h0 = bhi(v.x), h1 = bhi(v.y), h2 = bhi(v.z), h3 = bhi(v.w);
    *(uint2*)(g_xh + i) = make_uint2(pack2(h0, h1), pack2(h2, h3));
    *(uint2*)(g_xl + i) = make_uint2(pack2(blo(v.x, h0), blo(v.y, h1)),
                                     pack2(blo(v.z, h2), blo(v.w, h3)));
}

// BN1 fold: W1' = W1 * 2*gamma1[k] (split), b1eff = b1 + W1 @ beta1
__global__ __launch_bounds__(256) void k_foldw1(const float* __restrict__ w1)
{
    int i = blockIdx.x * 256 + threadIdx.x;    // 262144
    int k = i & 511;
    wsplit((size_t)WOFF_FF1 + i, w1[i] * (2.f * g_gamma1[k]));
}
__global__ __launch_bounds__(512) void k_foldb1(const float* __restrict__ w1,
                                                const float* __restrict__ b1)
{
    __shared__ float bs[512];
    int n = threadIdx.x;
    bs[n] = g_beta1[n];
    __syncthreads();
    float s = b1[n];
    const float* row = w1 + (size_t)n * 512;
    for (int k = 0; k < 512; k++) s += row[k] * bs[k];
    g_b1eff[n] = s;
}

// ===========================================================================
// BatchNorm finals + BN2 path (h recomputed from proj)
// ===========================================================================
__global__ __launch_bounds__(512) void k_bnfinal(const float* __restrict__ w,
                                                 const float* __restrict__ bias, int sel)
{
    int c = threadIdx.x;
    float s = 0.f, q = 0.f;
    for (int i = 0; i < 256; i++) { s += g_psum[i * 512 + c]; q += g_psq[i * 512 + c]; }
    float m   = s * (1.f / 32768.f);
    float var = q * (1.f / 32768.f) - m * m;
    float inv = rsqrtf(var + 1e-5f);
    float g   = inv * w[c];
    if (sel == 0) { g_gamma1[c] = g; g_beta1[c] = bias[c] - m * g; }
    else          { g_gamma[c]  = g; g_beta[c]  = bias[c] - m * g; }
}

// BN2 stats: t = 2*(h + ff2), h = 2*gamma1*p + beta1, p = ph+pl
__global__ __launch_bounds__(256) void k_bnstats2()
{
    int c = blockIdx.x * 256 + threadIdx.x;
    int chunk = blockIdx.y;
    int r0 = chunk * 128;
    float g1 = 2.f * g_gamma1[c], b1 = g_beta1[c];
    float s = 0.f, q = 0.f;
    for (int r = r0; r < r0 + 128; r++) {
        size_t i = (size_t)r * 512 + c;
        float p = __bfloat162float(g_ph[i]) + __bfloat162float(g_pl[i]);
        float t = 2.f * (g1 * p + b1 + g_arena[i]);
        s += t; q += t * t;
    }
    g_psum[chunk * 512 + c] = s;
    g_psq[chunk * 512 + c]  = q;
}

__global__ __launch_bounds__(256) void k_bnapply2(float* __restrict__ out)
{
    size_t i = ((size_t)blockIdx.x * 256 + threadIdx.x) * 4;
    int c = (int)(i & 511);
    float4 f = *(const float4*)(g_arena + i);
    uint2 hv = *(const uint2*)(g_ph + i);
    uint2 lv = *(const uint2*)(g_pl + i);
    const __nv_bfloat16* hp = (const __nv_bfloat16*)&hv;
    const __nv_bfloat16* lp = (const __nv_bfloat16*)&lv;
    float4 g1 = *(const float4*)&g_gamma1[c];
    float4 b1 = *(const float4*)&g_beta1[c];
    float4 g2 = *(const float4*)&g_gamma[c];
    float4 b2 = *(const float4*)&g_beta[c];
    float px = __bfloat162float(hp[0]) + __bfloat162float(lp[0]);
    float py = __bfloat162float(hp[1]) + __bfloat162float(lp[1]);
    float pz = __bfloat162float(hp[2]) + __bfloat162float(lp[2]);
    float pw = __bfloat162float(hp[3]) + __bfloat162float(lp[3]);
    float4 y;
    y.x = 2.f * (2.f * g1.x * px + b1.x + f.x) * g2.x + b2.x;
    y.y = 2.f * (2.f * g1.y * py + b1.y + f.y) * g2.y + b2.y;
    y.z = 2.f * (2.f * g1.z * pz + b1.z + f.z) * g2.z + b2.z;
    y.w = 2.f * (2.f * g1.w * pw + b1.w + f.w) * g2.w + b2.w;
    *(float4*)(out + i) = y;
}

// ===========================================================================
// Pipeline
// ===========================================================================
extern "C" void kernel_launch(void* const* d_in, const int* in_sizes, int n_in,
                              void* d_out, int out_size)
{
    const float* x    = (const float*)d_in[0];
    const float* Wq   = (const float*)d_in[1];
    const float* Wk   = (const float*)d_in[2];
    const float* Wv   = (const float*)d_in[3];
    const float* Wo   = (const float*)d_in[4];
    const float* n1w  = (const float*)d_in[5];
    const float* n1b  = (const float*)d_in[6];
    const float* n2w  = (const float*)d_in[7];
    const float* n2b  = (const float*)d_in[8];
    const float* ffw1 = (const float*)d_in[9];
    const float* ffb1 = (const float*)d_in[10];
    const float* ffw2 = (const float*)d_in[11];
    const float* ffb2 = (const float*)d_in[12];

    cudaFuncSetAttribute(k_mm_qkv3, cudaFuncAttributeMaxDynamicSharedMemorySize, QKV_SMEM);
    cudaFuncSetAttribute(k_attn_mma, cudaFuncAttributeMaxDynamicSharedMemorySize, ATTN_SMEM);

    // 0. prep
    k_prep_qkv<<<dim3(128, 24), 256>>>(Wq, Wk, Wv);
    k_prep_wo<<<1024, 256>>>(Wo);
    k_prep_ff2<<<1024, 256>>>(ffw2);
    k_prep_x<<<16384, 256>>>(x);

    // 1. fused QKV -> bf16 Q/K/Vt
    k_mm_qkv3<<<dim3(256, 8), 256, QKV_SMEM>>>();

    // 2. flash attention -> heads bf16 hi/lo
    k_attn_mma<<<dim3(4, 64, 8), 256, ATTN_SMEM>>>();

    // 3. output projection -> proj hi/lo + fused BN1 partial stats
    k_mm_bf<<<dim3(256, 8), 256>>>(0, nullptr);

    // 4. BN1 final -> gamma1/beta1; fold into FF1 weights + bias
    k_bnfinal<<<1, 512>>>(n1w, n1b, 0);
    k_foldw1<<<1024, 256>>>(ffw1);
    k_foldb1<<<1, 512>>>(ffw1, ffb1);

    // 5. FFN: ff1 = relu(proj @ W1'^T + b1eff) hi/lo; ff2 fp32
    k_mm_bf<<<dim3(256, 8), 256>>>(1, nullptr);
    k_mm_bf<<<dim3(256, 8), 256>>>(2, ffb2);

    // 6. BN2 -> d_out
    k_bnstats2<<<dim3(2, 256), 256>>>();
    k_bnfinal<<<1, 512>>>(n2w, n2b, 1);
    k_bnapply2<<<16384, 256>>>((float*)d_out);
}